// round 14
// baseline (speedup 1.0000x reference)
#include <cuda_runtime.h>
#include <cuda_fp16.h>
#include <cstdint>

#define Bb 2
#define Ss 2048
#define Dd 2048
#define KVH 8
#define QPG 4
#define HD 64
#define Mtot (Bb*Ss)            // 4096
#define NQ (KVH*QPG*HD)         // 2048
#define NKV (KVH*HD)            // 512
#define NTOT (NQ + 2*NKV)       // 3072

// ---------------- scratch (module-load static, no runtime allocs) ----------
__device__ __align__(16) unsigned short g_xh[(size_t)Mtot*Dd];    // x fp16
__device__ __align__(16) unsigned short g_wh[(size_t)NTOT*Dd];    // wq|wk|wv fp16
__device__ __align__(16) unsigned short g_oh[(size_t)Dd*NQ];      // wo fp16
__device__ __align__(16) unsigned short g_af[(size_t)Mtot*NQ];    // attn out fp16
__device__ __align__(16) unsigned short g_qh[(size_t)64*Ss*HD];   // [head][s][h]
__device__ __align__(16) unsigned short g_kh[(size_t)16*Ss*HD];   // [bg][s][h]
__device__ __align__(16) unsigned short g_vth[(size_t)16*HD*Ss];  // [bg][h][s]

// ---------------- helpers ---------------------------------------------------
__device__ __forceinline__ uint32_t s2u(const void* p){
    uint32_t a;
    asm("{ .reg .u64 t; cvta.to.shared.u64 t, %1; cvt.u32.u64 %0, t; }":"=r"(a):"l"(p));
    return a;
}
__device__ __forceinline__ void cp16(uint32_t d, const void* g){
    asm volatile("cp.async.cg.shared.global [%0], [%1], 16;" :: "r"(d), "l"(g));
}
__device__ __forceinline__ void ldm4(uint32_t* r, uint32_t addr){
    asm volatile("ldmatrix.sync.aligned.m8n8.x4.shared.b16 {%0,%1,%2,%3}, [%4];"
        : "=r"(r[0]), "=r"(r[1]), "=r"(r[2]), "=r"(r[3]) : "r"(addr));
}
__device__ __forceinline__ void mma16816(float* c, const uint32_t* a, const uint32_t* b){
    asm volatile("mma.sync.aligned.m16n8k16.row.col.f32.f16.f16.f32 "
        "{%0,%1,%2,%3}, {%4,%5,%6,%7}, {%8,%9}, {%0,%1,%2,%3};"
        : "+f"(c[0]), "+f"(c[1]), "+f"(c[2]), "+f"(c[3])
        : "r"(a[0]), "r"(a[1]), "r"(a[2]), "r"(a[3]), "r"(b[0]), "r"(b[1]));
}
__device__ __forceinline__ uint32_t packh(float lo, float hi){
    uint32_t r;
    asm("cvt.rn.f16x2.f32 %0, %1, %2;" : "=r"(r) : "f"(hi), "f"(lo));
    return r;
}

// ---------------- one-shot fp32 -> fp16 convert of all 5 tensors -----------
__global__ __launch_bounds__(256) void convert_all(
    const float4* __restrict__ x,  const float4* __restrict__ wq,
    const float4* __restrict__ wk, const float4* __restrict__ wv,
    const float4* __restrict__ wo,
    uint2* __restrict__ xh, uint2* __restrict__ wh, uint2* __restrict__ oh)
{
    int i = blockIdx.x*blockDim.x + threadIdx.x;
    const float4* s; uint2* d; int off;
    if (i < 2097152)      { s = x;  d = xh;           off = i; }
    else if (i < 3145728) { s = wq; d = wh;           off = i - 2097152; }
    else if (i < 3407872) { s = wk; d = wh + 1048576; off = i - 3145728; }
    else if (i < 3670016) { s = wv; d = wh + 1310720; off = i - 3407872; }
    else if (i < 4718592) { s = wo; d = oh;           off = i - 3670016; }
    else return;
    float4 v = s[off];
    d[off] = make_uint2(packh(v.x, v.y), packh(v.z, v.w));
}

// ---------------- GEMM tile constants (BK=32, 3-stage, 128 thr) ------------
#define T_ELEMS (128*40)
#define STG_ELEMS (2*T_ELEMS)
#define GEMM_SMEM (3*STG_ELEMS*2)   // 61440 bytes

// 128-thr / 4-warp (2x2) GEMM mainloop, warp tile 64x64, BK=32, 3 stages.
#define GEMM_MAINLOOP(Aptr, Bptr, Kd)                                          \
    auto prefetch = [&](int c){                                                \
        unsigned short* s = sm + (c % 3) * STG_ELEMS;                          \
        const int k0 = c << 5;                                                 \
        uint32_t so = tid * 40;                                                \
        const unsigned short* ga = Aptr + (size_t)(Mb + tid) * Kd + k0;        \
        const unsigned short* gb = Bptr + (size_t)(Nb + tid) * Kd + k0;        \
        cp16(s2u(s + so),                ga);                                  \
        cp16(s2u(s + so + 8),            ga + 8);                              \
        cp16(s2u(s + so + 16),           ga + 16);                             \
        cp16(s2u(s + so + 24),           ga + 24);                             \
        cp16(s2u(s + T_ELEMS + so),      gb);                                  \
        cp16(s2u(s + T_ELEMS + so + 8),  gb + 8);                              \
        cp16(s2u(s + T_ELEMS + so + 16), gb + 16);                             \
        cp16(s2u(s + T_ELEMS + so + 24), gb + 24);                             \
        asm volatile("cp.async.commit_group;" ::: "memory");                   \
    };                                                                         \
    const int a_row = wm*64 + ((lane>>3)&1)*8 + (lane&7);                      \
    const int a_kof = (lane>>4)*8;                                             \
    const int b_row = wn*64 + ((lane>>4)&1)*8 + (lane&7);                      \
    const int b_kof = ((lane>>3)&1)*8;                                         \
    prefetch(0);                                                               \
    prefetch(1);                                                               \
    for (int c = 0; c < NC; c++) {                                             \
        if (c + 1 < NC) { asm volatile("cp.async.wait_group 1;" ::: "memory"); }\
        else            { asm volatile("cp.async.wait_group 0;" ::: "memory"); }\
        __syncthreads();                                                       \
        if (c + 2 < NC) prefetch(c + 2);                                       \
        const unsigned short* s = sm + (c % 3) * STG_ELEMS;                    \
        _Pragma("unroll")                                                      \
        for (int kk = 0; kk < 2; kk++) {                                       \
            const int ak = kk*16 + a_kof, bk = kk*16 + b_kof;                  \
            uint32_t ah[4][4], bh[16];                                         \
            _Pragma("unroll")                                                  \
            for (int mt = 0; mt < 4; mt++)                                     \
                ldm4(ah[mt], s2u(s + (a_row + mt*16) * 40 + ak));              \
            _Pragma("unroll")                                                  \
            for (int np = 0; np < 4; np++)                                     \
                ldm4(&bh[np*4], s2u(s + T_ELEMS + (b_row + np*16) * 40 + bk)); \
            _Pragma("unroll")                                                  \
            for (int mt = 0; mt < 4; mt++)                                     \
                _Pragma("unroll")                                              \
                for (int nt = 0; nt < 8; nt++)                                 \
                    mma16816(acc[mt][nt], ah[mt], &bh[nt*2]);                  \
        }                                                                      \
    }

// ---------------- QKV GEMM with fused norm+rope+scatter epilogue -----------
__global__ __launch_bounds__(128) void qkv_mma(
    const unsigned short* __restrict__ A,
    const unsigned short* __restrict__ B,
    const float* __restrict__ qn, const float* __restrict__ kn,
    const int* __restrict__ pos_ids)
{
    extern __shared__ unsigned short sm[];
    const int tid = threadIdx.x, lane = tid & 31, wid = tid >> 5;
    const int wm = wid >> 1, wn = wid & 1;
    const int g = lane >> 2, t = lane & 3;
    const int nb = blockIdx.x, mb = blockIdx.y;
    const int Mb = mb * 128, Nb = nb * 128;
    const int NC = Dd >> 5;   // 64

    float acc[4][8][4];
#pragma unroll
    for (int mt = 0; mt < 4; mt++)
#pragma unroll
        for (int nt = 0; nt < 8; nt++)
#pragma unroll
            for (int r = 0; r < 4; r++) acc[mt][nt][r] = 0.f;

    GEMM_MAINLOOP(A, B, Dd)

    // ---- fused epilogue: stage tile as fp16 in smem ----
    __syncthreads();
    unsigned short* st = sm;                  // [128][132]
#pragma unroll
    for (int mt = 0; mt < 4; mt++) {
        int row = wm*64 + mt*16 + g;
        int colb = wn*64 + t*2;
#pragma unroll
        for (int nt = 0; nt < 8; nt++) {
            *(uint32_t*)&st[(size_t)row    *132 + colb + nt*8] = packh(acc[mt][nt][0], acc[mt][nt][1]);
            *(uint32_t*)&st[(size_t)(row+8)*132 + colb + nt*8] = packh(acc[mt][nt][2], acc[mt][nt][3]);
        }
    }
    __syncthreads();

    for (int u = tid; u < 256; u += 128) {
        if (nb >= 20) {
            // ---- V tiles: transpose-convert to g_vth[bg][h][s] ----
            int c  = u >> 1;                 // tile col 0..127
            int rh = (u & 1) * 64;           // row half
            int vcol = nb*128 + c - 2560;    // 0..511
            int kvg = vcol >> 6, h = vcol & 63;
            int m0 = Mb + rh;
            int b = m0 >> 11, s0 = m0 & 2047;
            unsigned short* dst = g_vth + ((size_t)(b*KVH + kvg)*HD + h)*Ss + s0;
#pragma unroll
            for (int i0 = 0; i0 < 64; i0 += 8) {
                uint32_t p[4];
#pragma unroll
                for (int j = 0; j < 4; j++) {
                    unsigned short va = st[(size_t)(rh + i0 + 2*j    )*132 + c];
                    unsigned short vb = st[(size_t)(rh + i0 + 2*j + 1)*132 + c];
                    p[j] = (uint32_t)va | ((uint32_t)vb << 16);
                }
                *(uint4*)(dst + i0) = make_uint4(p[0], p[1], p[2], p[3]);
            }
        } else {
            // ---- Q/K tiles: per-thread row-head rmsnorm + rope ----
            int row = u & 127, hd = (u >> 7) & 1;
            int m = Mb + row, b = m >> 11, s = m & 2047;
            uint32_t v2[32];
#pragma unroll
            for (int j = 0; j < 32; j++)
                v2[j] = *(uint32_t*)&st[(size_t)row*132 + hd*64 + j*2];
            float ssum = 0.f;
#pragma unroll
            for (int j = 0; j < 32; j++) {
                float2 f = __half22float2(*(__half2*)&v2[j]);
                ssum += f.x*f.x + f.y*f.y;
            }
            float inv = rsqrtf(ssum * (1.f/64.f) + 1e-5f);
            const float* w = (nb < 16) ? qn : kn;
            float pos = (float)pos_ids[s];
            unsigned short* dst;
            if (nb < 16) {
                int qh = nb*2 + hd;
                dst = g_qh + ((size_t)(b*32 + qh)*Ss + s)*HD;
            } else {
                int kh = (nb - 16)*2 + hd;
                dst = g_kh + ((size_t)(b*KVH + kh)*Ss + s)*HD;
            }
            uint32_t outp[32];
#pragma unroll
            for (int j = 0; j < 16; j++) {
                float2 lo2 = __half22float2(*(__half2*)&v2[j]);
                float2 hi2 = __half22float2(*(__half2*)&v2[j+16]);
                float x1a = lo2.x * inv * w[2*j];
                float x1b = lo2.y * inv * w[2*j+1];
                float x2a = hi2.x * inv * w[2*j+32];
                float x2b = hi2.y * inv * w[2*j+33];
                float o1a = x1a, o1b = x1b, o2a = x2a, o2b = x2b;
                if (j < 8) {
                    float fA = pos * exp2f(-0.625f * (float)(2*j));
                    float fB = pos * exp2f(-0.625f * (float)(2*j+1));
                    float snA = sinf(fA), csA = cosf(fA);
                    float snB = sinf(fB), csB = cosf(fB);
                    o1a = x1a*csA - x2a*snA;  o2a = x2a*csA + x1a*snA;
                    o1b = x1b*csB - x2b*snB;  o2b = x2b*csB + x1b*snB;
                }
                outp[j]      = packh(o1a, o1b);
                outp[j + 16] = packh(o2a, o2b);
            }
#pragma unroll
            for (int i0 = 0; i0 < 32; i0 += 4)
                *(uint4*)(dst + i0*2) = make_uint4(outp[i0], outp[i0+1], outp[i0+2], outp[i0+3]);
        }
    }
}

// ---------------- generic HMMA GEMM (out-projection) -----------------------
__global__ __launch_bounds__(128) void gemm_mma(
    const unsigned short* __restrict__ A,
    const unsigned short* __restrict__ B,
    float* __restrict__ C, int Kd, int ldc)
{
    extern __shared__ unsigned short sm[];
    const int tid = threadIdx.x, lane = tid & 31, wid = tid >> 5;
    const int wm = wid >> 1, wn = wid & 1;
    const int g = lane >> 2, t = lane & 3;
    const int Mb = blockIdx.y * 128, Nb = blockIdx.x * 128;
    const int NC = Kd >> 5;

    float acc[4][8][4];
#pragma unroll
    for (int mt = 0; mt < 4; mt++)
#pragma unroll
        for (int nt = 0; nt < 8; nt++)
#pragma unroll
            for (int r = 0; r < 4; r++) acc[mt][nt][r] = 0.f;

    GEMM_MAINLOOP(A, B, Kd)

#pragma unroll
    for (int mt = 0; mt < 4; mt++) {
        int row = Mb + wm*64 + mt*16 + g;
#pragma unroll
        for (int nt = 0; nt < 8; nt++) {
            int col = Nb + wn*64 + nt*8 + t*2;
            *(float2*)&C[(size_t)row * ldc + col] =
                make_float2(acc[mt][nt][0], acc[mt][nt][1]);
            *(float2*)&C[(size_t)(row + 8) * ldc + col] =
                make_float2(acc[mt][nt][2], acc[mt][nt][3]);
        }
    }
}

// ---------------- MMA flash attention (fp16 1-term, unchanged) -------------
#define QT (128*72)
#define KT (64*72)
#define AST (2*KT)
#define ATT_SMEM ((QT + 2*AST)*2)

__global__ __launch_bounds__(256, 2) void attn_mma()
{
    extern __shared__ unsigned short sm[];
    const int tid = threadIdx.x, lane = tid & 31, wm = tid >> 5;
    const int g = lane >> 2, t = lane & 3;
    const int head = blockIdx.x;
    const int qb = 15 - (int)blockIdx.y;
    const int b = head >> 5, gp = head & 31, kvg = gp >> 2;
    const int rb = qb * 128 + wm * 16;

    const unsigned short* Qh = g_qh + ((size_t)head * Ss + qb * 128) * HD;
    const unsigned short* Kh = g_kh + (size_t)(b * KVH + kvg) * Ss * HD;
    const unsigned short* Vth = g_vth + (size_t)(b * KVH + kvg) * HD * Ss;

    unsigned short* QH = sm;

    {
        int row = tid >> 1, cbq = (tid & 1) * 4;
#pragma unroll
        for (int c = cbq; c < cbq + 4; c++) {
            uint32_t so = row * 72 + c * 8;
            cp16(s2u(QH + so), Qh + row * 64 + c * 8);
        }
        asm volatile("cp.async.commit_group;" ::: "memory");
    }

    auto prefetchKV = [&](int kt){
        unsigned short* st = sm + QT + (kt & 1) * AST;
        int row = tid >> 2, cb2 = (tid & 3) * 2;
#pragma unroll
        for (int c = cb2; c < cb2 + 2; c++) {
            uint32_t so = row * 72 + c * 8;
            cp16(s2u(st +      so), Kh  + (size_t)(kt * 64 + row) * HD + c * 8);
            cp16(s2u(st + KT + so), Vth + (size_t)row * Ss + kt * 64 + c * 8);
        }
        asm volatile("cp.async.commit_group;" ::: "memory");
    };

    prefetchKV(0);

    const int ktmax = 2 * qb + 1;
    float m0 = -1e30f, m1 = -1e30f, l0 = 0.f, l1 = 0.f;
    float oac[8][4];
#pragma unroll
    for (int nt = 0; nt < 8; nt++)
#pragma unroll
        for (int r = 0; r < 4; r++) oac[nt][r] = 0.f;
    uint32_t qfh[4][4];

    const int n_row = ((lane>>4)&1)*8 + (lane&7);
    const int n_kof = ((lane>>3)&1)*8;

    for (int kt = 0; kt <= ktmax; kt++) {
        if (kt < ktmax) {
            prefetchKV(kt + 1);
            asm volatile("cp.async.wait_group 1;" ::: "memory");
        } else {
            asm volatile("cp.async.wait_group 0;" ::: "memory");
        }
        __syncthreads();

        if (kt == 0) {
            const int qa_row = wm*16 + ((lane>>3)&1)*8 + (lane&7);
            const int qa_kof = (lane>>4)*8;
#pragma unroll
            for (int ks = 0; ks < 4; ks++)
                ldm4(qfh[ks], s2u(QH + qa_row * 72 + ks*16 + qa_kof));
        }

        if (kt * 64 <= rb + 15) {
            const unsigned short* KH = sm + QT + (kt & 1) * AST;
            const unsigned short* VH = KH + KT;

            float sc[8][4];
#pragma unroll
            for (int nt = 0; nt < 8; nt++)
#pragma unroll
                for (int r = 0; r < 4; r++) sc[nt][r] = 0.f;
#pragma unroll
            for (int ks = 0; ks < 4; ks++) {
                uint32_t bh[16];
#pragma unroll
                for (int np = 0; np < 4; np++)
                    ldm4(&bh[np*4], s2u(KH + (np*16 + n_row) * 72 + ks*16 + n_kof));
#pragma unroll
                for (int nt = 0; nt < 8; nt++)
                    mma16816(sc[nt], qfh[ks], &bh[nt*2]);
            }

            const bool needmask = (kt * 64 + 63 > rb);
#pragma unroll
            for (int nt = 0; nt < 8; nt++) {
#pragma unroll
                for (int r = 0; r < 4; r++) {
                    float d = sc[nt][r];
                    float z = d * 0.0025f, z2 = z * z;
                    float pq = 1.f + z2*(-0.33333334f + z2*(0.13333334f - z2*0.05396825f));
                    float v = d * 0.125f * pq;
                    if (needmask) {
                        int col = kt*64 + nt*8 + (t<<1) + (r & 1);
                        int row = rb + g + ((r >> 1) << 3);
                        if (col > row) v = -1e30f;
                    }
                    sc[nt][r] = v;
                }
            }

            float tm0 = -1e30f, tm1 = -1e30f;
#pragma unroll
            for (int nt = 0; nt < 8; nt++) {
                tm0 = fmaxf(tm0, fmaxf(sc[nt][0], sc[nt][1]));
                tm1 = fmaxf(tm1, fmaxf(sc[nt][2], sc[nt][3]));
            }
            tm0 = fmaxf(tm0, __shfl_xor_sync(0xffffffffu, tm0, 1));
            tm0 = fmaxf(tm0, __shfl_xor_sync(0xffffffffu, tm0, 2));
            tm1 = fmaxf(tm1, __shfl_xor_sync(0xffffffffu, tm1, 1));
            tm1 = fmaxf(tm1, __shfl_xor_sync(0xffffffffu, tm1, 2));
            float nm0 = fmaxf(m0, tm0), nm1 = fmaxf(m1, tm1);
            float a0 = __expf(m0 - nm0), a1 = __expf(m1 - nm1);
            m0 = nm0; m1 = nm1;
            float rs0 = 0.f, rs1 = 0.f;
#pragma unroll
            for (int nt = 0; nt < 8; nt++) {
                sc[nt][0] = __expf(sc[nt][0] - nm0);
                sc[nt][1] = __expf(sc[nt][1] - nm0);
                sc[nt][2] = __expf(sc[nt][2] - nm1);
                sc[nt][3] = __expf(sc[nt][3] - nm1);
                rs0 += sc[nt][0] + sc[nt][1];
                rs1 += sc[nt][2] + sc[nt][3];
            }
            rs0 += __shfl_xor_sync(0xffffffffu, rs0, 1);
            rs0 += __shfl_xor_sync(0xffffffffu, rs0, 2);
            rs1 += __shfl_xor_sync(0xffffffffu, rs1, 1);
            rs1 += __shfl_xor_sync(0xffffffffu, rs1, 2);
            l0 = l0 * a0 + rs0;
            l1 = l1 * a1 + rs1;
#pragma unroll
            for (int nt = 0; nt < 8; nt++) {
                oac[nt][0] *= a0; oac[nt][1] *= a0;
                oac[nt][2] *= a1; oac[nt][3] *= a1;
            }

#pragma unroll
            for (int ks = 0; ks < 4; ks++) {
                uint32_t pha[4];
                pha[0] = packh(sc[2*ks][0],   sc[2*ks][1]);
                pha[1] = packh(sc[2*ks][2],   sc[2*ks][3]);
                pha[2] = packh(sc[2*ks+1][0], sc[2*ks+1][1]);
                pha[3] = packh(sc[2*ks+1][2], sc[2*ks+1][3]);
                uint32_t vh[16];
#pragma unroll
                for (int np = 0; np < 4; np++)
                    ldm4(&vh[np*4], s2u(VH + (np*16 + n_row) * 72 + ks*16 + n_kof));
#pragma unroll
                for (int nt = 0; nt < 8; nt++)
                    mma16816(oac[nt], pha, &vh[nt*2]);
            }
        }
        __syncthreads();
    }

    float i0 = 1.f / l0, i1 = 1.f / l1;
    size_t r0 = ((size_t)b * Ss + rb + g) * 2048;
    size_t r1 = ((size_t)b * Ss + rb + 8 + g) * 2048;
#pragma unroll
    for (int nt = 0; nt < 8; nt++) {
        int col = gp * 64 + nt * 8 + t * 2;
        *(uint32_t*)&g_af[r0 + col] = packh(oac[nt][0] * i0, oac[nt][1] * i0);
        *(uint32_t*)&g_af[r1 + col] = packh(oac[nt][2] * i1, oac[nt][3] * i1);
    }
}

// ---------------- launch ---------------------------------------------------
extern "C" void kernel_launch(void* const* d_in, const int* in_sizes, int n_in,
                              void* d_out, int out_size)
{
    const float* x  = (const float*)d_in[0];
    const float* wq = (const float*)d_in[1];
    const float* wk = (const float*)d_in[2];
    const float* wv = (const float*)d_in[3];
    const float* wo = (const float*)d_in[4];
    const float* qn = (const float*)d_in[5];
    const float* kn = (const float*)d_in[6];
    const int* pos  = (const int*)d_in[7];
    float* out = (float*)d_out;

    unsigned short *xh, *wh, *oh, *af;
    cudaGetSymbolAddress((void**)&xh, g_xh);
    cudaGetSymbolAddress((void**)&wh, g_wh);
    cudaGetSymbolAddress((void**)&oh, g_oh);
    cudaGetSymbolAddress((void**)&af, g_af);

    cudaFuncSetAttribute(qkv_mma,  cudaFuncAttributeMaxDynamicSharedMemorySize, GEMM_SMEM);
    cudaFuncSetAttribute(gemm_mma, cudaFuncAttributeMaxDynamicSharedMemorySize, GEMM_SMEM);
    cudaFuncSetAttribute(attn_mma, cudaFuncAttributeMaxDynamicSharedMemorySize, ATT_SMEM);

    convert_all<<<18432, 256>>>((const float4*)x, (const float4*)wq,
                                (const float4*)wk, (const float4*)wv,
                                (const float4*)wo,
                                (uint2*)xh, (uint2*)wh, (uint2*)oh);

    qkv_mma<<<dim3(24, 32), 128, GEMM_SMEM>>>(xh, wh, qn, kn, pos);
    attn_mma<<<dim3(64, 16), 256, ATT_SMEM>>>();
    gemm_mma<<<dim3(16, 32), 128, GEMM_SMEM>>>(af, oh, out, Dd, Dd);
}

// round 15
// speedup vs baseline: 1.2551x; 1.2551x over previous
#include <cuda_runtime.h>
#include <cuda_fp16.h>
#include <cstdint>

#define Bb 2
#define Ss 2048
#define Dd 2048
#define KVH 8
#define QPG 4
#define HD 64
#define Mtot (Bb*Ss)            // 4096
#define NQ (KVH*QPG*HD)         // 2048
#define NKV (KVH*HD)            // 512
#define NTOT (NQ + 2*NKV)       // 3072

// ---------------- scratch (module-load static, no runtime allocs) ----------
__device__ __align__(16) unsigned short g_xh[(size_t)Mtot*Dd];    // x fp16
__device__ __align__(16) unsigned short g_wh[(size_t)NTOT*Dd];    // wq|wk|wv fp16
__device__ __align__(16) unsigned short g_oh[(size_t)Dd*NQ];      // wo fp16
__device__ __align__(16) unsigned short g_af[(size_t)Mtot*NQ];    // attn out fp16
__device__ __align__(16) unsigned short g_qh[(size_t)64*Ss*HD];   // [head][s][h]
__device__ __align__(16) unsigned short g_kh[(size_t)16*Ss*HD];   // [bg][s][h]
__device__ __align__(16) unsigned short g_vth[(size_t)16*HD*Ss];  // [bg][h][s]

// ---------------- helpers ---------------------------------------------------
__device__ __forceinline__ uint32_t s2u(const void* p){
    uint32_t a;
    asm("{ .reg .u64 t; cvta.to.shared.u64 t, %1; cvt.u32.u64 %0, t; }":"=r"(a):"l"(p));
    return a;
}
__device__ __forceinline__ void cp16(uint32_t d, const void* g){
    asm volatile("cp.async.cg.shared.global [%0], [%1], 16;" :: "r"(d), "l"(g));
}
__device__ __forceinline__ void ldm4(uint32_t* r, uint32_t addr){
    asm volatile("ldmatrix.sync.aligned.m8n8.x4.shared.b16 {%0,%1,%2,%3}, [%4];"
        : "=r"(r[0]), "=r"(r[1]), "=r"(r[2]), "=r"(r[3]) : "r"(addr));
}
__device__ __forceinline__ void mma16816(float* c, const uint32_t* a, const uint32_t* b){
    asm volatile("mma.sync.aligned.m16n8k16.row.col.f32.f16.f16.f32 "
        "{%0,%1,%2,%3}, {%4,%5,%6,%7}, {%8,%9}, {%0,%1,%2,%3};"
        : "+f"(c[0]), "+f"(c[1]), "+f"(c[2]), "+f"(c[3])
        : "r"(a[0]), "r"(a[1]), "r"(a[2]), "r"(a[3]), "r"(b[0]), "r"(b[1]));
}
__device__ __forceinline__ uint32_t packh(float lo, float hi){
    uint32_t r;
    asm("cvt.rn.f16x2.f32 %0, %1, %2;" : "=r"(r) : "f"(hi), "f"(lo));
    return r;
}

// ---------------- one-shot fp32 -> fp16 convert of all 5 tensors -----------
__global__ __launch_bounds__(256) void convert_all(
    const float4* __restrict__ x,  const float4* __restrict__ wq,
    const float4* __restrict__ wk, const float4* __restrict__ wv,
    const float4* __restrict__ wo,
    uint2* __restrict__ xh, uint2* __restrict__ wh, uint2* __restrict__ oh)
{
    int i = blockIdx.x*blockDim.x + threadIdx.x;
    const float4* s; uint2* d; int off;
    if (i < 2097152)      { s = x;  d = xh;           off = i; }
    else if (i < 3145728) { s = wq; d = wh;           off = i - 2097152; }
    else if (i < 3407872) { s = wk; d = wh + 1048576; off = i - 3145728; }
    else if (i < 3670016) { s = wv; d = wh + 1310720; off = i - 3407872; }
    else if (i < 4718592) { s = wo; d = oh;           off = i - 3670016; }
    else return;
    float4 v = s[off];
    d[off] = make_uint2(packh(v.x, v.y), packh(v.z, v.w));
}

// ---------------- GEMM tile constants (R11 best: BK=32, 3-stage) -----------
#define T_ELEMS (128*40)
#define STG_ELEMS (2*T_ELEMS)
#define GEMM_SMEM (3*STG_ELEMS*2)   // 61440 bytes

// 256-thr / 8-warp (4x2) GEMM mainloop, warp tile 32x64, BK=32, 3 stages.
#define GEMM_MAINLOOP(Aptr, Bptr, Kd)                                          \
    const int lrow = tid >> 1, lc2 = (tid & 1) * 2;                            \
    auto prefetch = [&](int c){                                                \
        unsigned short* s = sm + (c % 3) * STG_ELEMS;                          \
        const int k0 = c << 5;                                                 \
        uint32_t so = lrow * 40 + lc2 * 8;                                     \
        const unsigned short* ga = Aptr + (size_t)(Mb + lrow) * Kd + k0 + lc2 * 8; \
        const unsigned short* gb = Bptr + (size_t)(Nb + lrow) * Kd + k0 + lc2 * 8; \
        cp16(s2u(s + so),               ga);                                   \
        cp16(s2u(s + so + 8),           ga + 8);                               \
        cp16(s2u(s + T_ELEMS + so),     gb);                                   \
        cp16(s2u(s + T_ELEMS + so + 8), gb + 8);                               \
        asm volatile("cp.async.commit_group;" ::: "memory");                   \
    };                                                                         \
    const int a_row = wm*32 + ((lane>>3)&1)*8 + (lane&7);                      \
    const int a_kof = (lane>>4)*8;                                             \
    const int b_row = wn*64 + ((lane>>4)&1)*8 + (lane&7);                      \
    const int b_kof = ((lane>>3)&1)*8;                                         \
    prefetch(0);                                                               \
    prefetch(1);                                                               \
    for (int c = 0; c < NC; c++) {                                             \
        if (c + 1 < NC) { asm volatile("cp.async.wait_group 1;" ::: "memory"); }\
        else            { asm volatile("cp.async.wait_group 0;" ::: "memory"); }\
        __syncthreads();                                                       \
        if (c + 2 < NC) prefetch(c + 2);                                       \
        const unsigned short* s = sm + (c % 3) * STG_ELEMS;                    \
        _Pragma("unroll")                                                      \
        for (int kk = 0; kk < 2; kk++) {                                       \
            const int ak = kk*16 + a_kof, bk = kk*16 + b_kof;                  \
            uint32_t ah[2][4], bh[16];                                         \
            _Pragma("unroll")                                                  \
            for (int mt = 0; mt < 2; mt++)                                     \
                ldm4(ah[mt], s2u(s + (a_row + mt*16) * 40 + ak));              \
            _Pragma("unroll")                                                  \
            for (int np = 0; np < 4; np++)                                     \
                ldm4(&bh[np*4], s2u(s + T_ELEMS + (b_row + np*16) * 40 + bk)); \
            _Pragma("unroll")                                                  \
            for (int mt = 0; mt < 2; mt++)                                     \
                _Pragma("unroll")                                              \
                for (int nt = 0; nt < 8; nt++)                                 \
                    mma16816(acc[mt][nt], ah[mt], &bh[nt*2]);                  \
        }                                                                      \
    }

// ---------------- QKV GEMM with fused norm+rope+scatter epilogue -----------
__global__ __launch_bounds__(256, 2) void qkv_mma(
    const unsigned short* __restrict__ A,
    const unsigned short* __restrict__ B,
    const float* __restrict__ qn, const float* __restrict__ kn,
    const int* __restrict__ pos_ids)
{
    extern __shared__ unsigned short sm[];
    const int tid = threadIdx.x, lane = tid & 31, wid = tid >> 5;
    const int wm = wid >> 1, wn = wid & 1;
    const int g = lane >> 2, t = lane & 3;
    const int nb = blockIdx.x, mb = blockIdx.y;
    const int Mb = mb * 128, Nb = nb * 128;
    const int NC = Dd >> 5;   // 64

    float acc[2][8][4];
#pragma unroll
    for (int mt = 0; mt < 2; mt++)
#pragma unroll
        for (int nt = 0; nt < 8; nt++)
#pragma unroll
            for (int r = 0; r < 4; r++) acc[mt][nt][r] = 0.f;

    GEMM_MAINLOOP(A, B, Dd)

    // ---- fused epilogue: stage tile as fp16 in smem ----
    __syncthreads();
    unsigned short* st = sm;                  // [128][132]
#pragma unroll
    for (int mt = 0; mt < 2; mt++) {
        int row = wm*32 + mt*16 + g;
        int colb = wn*64 + t*2;
#pragma unroll
        for (int nt = 0; nt < 8; nt++) {
            *(uint32_t*)&st[(size_t)row    *132 + colb + nt*8] = packh(acc[mt][nt][0], acc[mt][nt][1]);
            *(uint32_t*)&st[(size_t)(row+8)*132 + colb + nt*8] = packh(acc[mt][nt][2], acc[mt][nt][3]);
        }
    }
    __syncthreads();

    if (nb >= 20) {
        // ---- V tiles: transpose-convert to g_vth[bg][h][s] ----
        int c  = tid >> 1;                 // tile col 0..127
        int rh = (tid & 1) * 64;           // row half
        int vcol = nb*128 + c - 2560;      // 0..511
        int kvg = vcol >> 6, h = vcol & 63;
        int m0 = Mb + rh;
        int b = m0 >> 11, s0 = m0 & 2047;
        unsigned short* dst = g_vth + ((size_t)(b*KVH + kvg)*HD + h)*Ss + s0;
#pragma unroll
        for (int i0 = 0; i0 < 64; i0 += 8) {
            uint32_t p[4];
#pragma unroll
            for (int j = 0; j < 4; j++) {
                unsigned short va = st[(size_t)(rh + i0 + 2*j    )*132 + c];
                unsigned short vb = st[(size_t)(rh + i0 + 2*j + 1)*132 + c];
                p[j] = (uint32_t)va | ((uint32_t)vb << 16);
            }
            *(uint4*)(dst + i0) = make_uint4(p[0], p[1], p[2], p[3]);
        }
    } else {
        // ---- Q/K tiles: per-thread row-head rmsnorm + rope ----
        int row = tid & 127, hd = (tid >> 7) & 1;
        int m = Mb + row, b = m >> 11, s = m & 2047;
        uint32_t v2[32];
#pragma unroll
        for (int j = 0; j < 32; j++)
            v2[j] = *(uint32_t*)&st[(size_t)row*132 + hd*64 + j*2];
        float ssum = 0.f;
#pragma unroll
        for (int j = 0; j < 32; j++) {
            float2 f = __half22float2(*(__half2*)&v2[j]);
            ssum += f.x*f.x + f.y*f.y;
        }
        float inv = rsqrtf(ssum * (1.f/64.f) + 1e-5f);
        const float* w = (nb < 16) ? qn : kn;
        float pos = (float)pos_ids[s];
        unsigned short* dst;
        if (nb < 16) {
            int qh = nb*2 + hd;
            dst = g_qh + ((size_t)(b*32 + qh)*Ss + s)*HD;
        } else {
            int kh = (nb - 16)*2 + hd;
            dst = g_kh + ((size_t)(b*KVH + kh)*Ss + s)*HD;
        }
        uint32_t outp[32];
#pragma unroll
        for (int j = 0; j < 16; j++) {
            float2 lo2 = __half22float2(*(__half2*)&v2[j]);
            float2 hi2 = __half22float2(*(__half2*)&v2[j+16]);
            float x1a = lo2.x * inv * w[2*j];
            float x1b = lo2.y * inv * w[2*j+1];
            float x2a = hi2.x * inv * w[2*j+32];
            float x2b = hi2.y * inv * w[2*j+33];
            float o1a = x1a, o1b = x1b, o2a = x2a, o2b = x2b;
            if (j < 8) {
                float fA = pos * exp2f(-0.625f * (float)(2*j));
                float fB = pos * exp2f(-0.625f * (float)(2*j+1));
                float snA = sinf(fA), csA = cosf(fA);
                float snB = sinf(fB), csB = cosf(fB);
                o1a = x1a*csA - x2a*snA;  o2a = x2a*csA + x1a*snA;
                o1b = x1b*csB - x2b*snB;  o2b = x2b*csB + x1b*snB;
            }
            outp[j]      = packh(o1a, o1b);
            outp[j + 16] = packh(o2a, o2b);
        }
#pragma unroll
        for (int i0 = 0; i0 < 32; i0 += 4)
            *(uint4*)(dst + i0*2) = make_uint4(outp[i0], outp[i0+1], outp[i0+2], outp[i0+3]);
    }
}

// ---------------- generic HMMA GEMM (out-projection) -----------------------
__global__ __launch_bounds__(256, 2) void gemm_mma(
    const unsigned short* __restrict__ A,
    const unsigned short* __restrict__ B,
    float* __restrict__ C, int Kd, int ldc)
{
    extern __shared__ unsigned short sm[];
    const int tid = threadIdx.x, lane = tid & 31, wid = tid >> 5;
    const int wm = wid >> 1, wn = wid & 1;
    const int g = lane >> 2, t = lane & 3;
    const int Mb = blockIdx.y * 128, Nb = blockIdx.x * 128;
    const int NC = Kd >> 5;

    float acc[2][8][4];
#pragma unroll
    for (int mt = 0; mt < 2; mt++)
#pragma unroll
        for (int nt = 0; nt < 8; nt++)
#pragma unroll
            for (int r = 0; r < 4; r++) acc[mt][nt][r] = 0.f;

    GEMM_MAINLOOP(A, B, Kd)

#pragma unroll
    for (int mt = 0; mt < 2; mt++) {
        int row = Mb + wm*32 + mt*16 + g;
#pragma unroll
        for (int nt = 0; nt < 8; nt++) {
            int col = Nb + wn*64 + nt*8 + t*2;
            *(float2*)&C[(size_t)row * ldc + col] =
                make_float2(acc[mt][nt][0], acc[mt][nt][1]);
            *(float2*)&C[(size_t)(row + 8) * ldc + col] =
                make_float2(acc[mt][nt][2], acc[mt][nt][3]);
        }
    }
}

// ---------------- MMA flash attention (single barrier per tile) ------------
#define QT (128*72)
#define KT (64*72)
#define AST (2*KT)
#define ATT_SMEM ((QT + 2*AST)*2)

__global__ __launch_bounds__(256, 2) void attn_mma()
{
    extern __shared__ unsigned short sm[];
    const int tid = threadIdx.x, lane = tid & 31, wm = tid >> 5;
    const int g = lane >> 2, t = lane & 3;
    const int head = blockIdx.x;
    const int qb = 15 - (int)blockIdx.y;
    const int b = head >> 5, gp = head & 31, kvg = gp >> 2;
    const int rb = qb * 128 + wm * 16;

    const unsigned short* Qh = g_qh + ((size_t)head * Ss + qb * 128) * HD;
    const unsigned short* Kh = g_kh + (size_t)(b * KVH + kvg) * Ss * HD;
    const unsigned short* Vth = g_vth + (size_t)(b * KVH + kvg) * HD * Ss;

    unsigned short* QH = sm;

    {   // prefetch Q (group 0)
        int row = tid >> 1, cbq = (tid & 1) * 4;
#pragma unroll
        for (int c = cbq; c < cbq + 4; c++) {
            uint32_t so = row * 72 + c * 8;
            cp16(s2u(QH + so), Qh + row * 64 + c * 8);
        }
        asm volatile("cp.async.commit_group;" ::: "memory");
    }

    auto prefetchKV = [&](int kt){
        unsigned short* st = sm + QT + (kt & 1) * AST;
        int row = tid >> 2, cb2 = (tid & 3) * 2;
#pragma unroll
        for (int c = cb2; c < cb2 + 2; c++) {
            uint32_t so = row * 72 + c * 8;
            cp16(s2u(st +      so), Kh  + (size_t)(kt * 64 + row) * HD + c * 8);
            cp16(s2u(st + KT + so), Vth + (size_t)row * Ss + kt * 64 + c * 8);
        }
        asm volatile("cp.async.commit_group;" ::: "memory");
    };

    prefetchKV(0);

    const int ktmax = 2 * qb + 1;
    float m0 = -1e30f, m1 = -1e30f, l0 = 0.f, l1 = 0.f;
    float oac[8][4];
#pragma unroll
    for (int nt = 0; nt < 8; nt++)
#pragma unroll
        for (int r = 0; r < 4; r++) oac[nt][r] = 0.f;
    uint32_t qfh[4][4];

    const int n_row = ((lane>>4)&1)*8 + (lane&7);
    const int n_kof = ((lane>>3)&1)*8;

    for (int kt = 0; kt <= ktmax; kt++) {
        // single barrier per tile: wait all in-flight (stage kt [+Q at kt=0]),
        // THEN barrier, THEN issue next prefetch (hazard-free: all warps have
        // finished reading stage (kt+1)&1 from iteration kt-1).
        asm volatile("cp.async.wait_group 0;" ::: "memory");
        __syncthreads();
        if (kt < ktmax) prefetchKV(kt + 1);

        if (kt == 0) {
            const int qa_row = wm*16 + ((lane>>3)&1)*8 + (lane&7);
            const int qa_kof = (lane>>4)*8;
#pragma unroll
            for (int ks = 0; ks < 4; ks++)
                ldm4(qfh[ks], s2u(QH + qa_row * 72 + ks*16 + qa_kof));
        }

        if (kt * 64 <= rb + 15) {
            const unsigned short* KH = sm + QT + (kt & 1) * AST;
            const unsigned short* VH = KH + KT;

            float sc[8][4];
#pragma unroll
            for (int nt = 0; nt < 8; nt++)
#pragma unroll
                for (int r = 0; r < 4; r++) sc[nt][r] = 0.f;
#pragma unroll
            for (int ks = 0; ks < 4; ks++) {
                uint32_t bh[16];
#pragma unroll
                for (int np = 0; np < 4; np++)
                    ldm4(&bh[np*4], s2u(KH + (np*16 + n_row) * 72 + ks*16 + n_kof));
#pragma unroll
                for (int nt = 0; nt < 8; nt++)
                    mma16816(sc[nt], qfh[ks], &bh[nt*2]);
            }

            const bool needmask = (kt * 64 + 63 > rb);
#pragma unroll
            for (int nt = 0; nt < 8; nt++) {
#pragma unroll
                for (int r = 0; r < 4; r++) {
                    float d = sc[nt][r];
                    float z = d * 0.0025f, z2 = z * z;
                    float pq = 1.f + z2*(-0.33333334f + z2*(0.13333334f - z2*0.05396825f));
                    float v = d * 0.125f * pq;
                    if (needmask) {
                        int col = kt*64 + nt*8 + (t<<1) + (r & 1);
                        int row = rb + g + ((r >> 1) << 3);
                        if (col > row) v = -1e30f;
                    }
                    sc[nt][r] = v;
                }
            }

            float tm0 = -1e30f, tm1 = -1e30f;
#pragma unroll
            for (int nt = 0; nt < 8; nt++) {
                tm0 = fmaxf(tm0, fmaxf(sc[nt][0], sc[nt][1]));
                tm1 = fmaxf(tm1, fmaxf(sc[nt][2], sc[nt][3]));
            }
            tm0 = fmaxf(tm0, __shfl_xor_sync(0xffffffffu, tm0, 1));
            tm0 = fmaxf(tm0, __shfl_xor_sync(0xffffffffu, tm0, 2));
            tm1 = fmaxf(tm1, __shfl_xor_sync(0xffffffffu, tm1, 1));
            tm1 = fmaxf(tm1, __shfl_xor_sync(0xffffffffu, tm1, 2));
            float nm0 = fmaxf(m0, tm0), nm1 = fmaxf(m1, tm1);
            float a0 = __expf(m0 - nm0), a1 = __expf(m1 - nm1);
            m0 = nm0; m1 = nm1;
            float rs0 = 0.f, rs1 = 0.f;
#pragma unroll
            for (int nt = 0; nt < 8; nt++) {
                sc[nt][0] = __expf(sc[nt][0] - nm0);
                sc[nt][1] = __expf(sc[nt][1] - nm0);
                sc[nt][2] = __expf(sc[nt][2] - nm1);
                sc[nt][3] = __expf(sc[nt][3] - nm1);
                rs0 += sc[nt][0] + sc[nt][1];
                rs1 += sc[nt][2] + sc[nt][3];
            }
            rs0 += __shfl_xor_sync(0xffffffffu, rs0, 1);
            rs0 += __shfl_xor_sync(0xffffffffu, rs0, 2);
            rs1 += __shfl_xor_sync(0xffffffffu, rs1, 1);
            rs1 += __shfl_xor_sync(0xffffffffu, rs1, 2);
            l0 = l0 * a0 + rs0;
            l1 = l1 * a1 + rs1;
#pragma unroll
            for (int nt = 0; nt < 8; nt++) {
                oac[nt][0] *= a0; oac[nt][1] *= a0;
                oac[nt][2] *= a1; oac[nt][3] *= a1;
            }

#pragma unroll
            for (int ks = 0; ks < 4; ks++) {
                uint32_t pha[4];
                pha[0] = packh(sc[2*ks][0],   sc[2*ks][1]);
                pha[1] = packh(sc[2*ks][2],   sc[2*ks][3]);
                pha[2] = packh(sc[2*ks+1][0], sc[2*ks+1][1]);
                pha[3] = packh(sc[2*ks+1][2], sc[2*ks+1][3]);
                uint32_t vh[16];
#pragma unroll
                for (int np = 0; np < 4; np++)
                    ldm4(&vh[np*4], s2u(VH + (np*16 + n_row) * 72 + ks*16 + n_kof));
#pragma unroll
                for (int nt = 0; nt < 8; nt++)
                    mma16816(oac[nt], pha, &vh[nt*2]);
            }
        }
    }

    float i0 = 1.f / l0, i1 = 1.f / l1;
    size_t r0 = ((size_t)b * Ss + rb + g) * 2048;
    size_t r1 = ((size_t)b * Ss + rb + 8 + g) * 2048;
#pragma unroll
    for (int nt = 0; nt < 8; nt++) {
        int col = gp * 64 + nt * 8 + t * 2;
        *(uint32_t*)&g_af[r0 + col] = packh(oac[nt][0] * i0, oac[nt][1] * i0);
        *(uint32_t*)&g_af[r1 + col] = packh(oac[nt][2] * i1, oac[nt][3] * i1);
    }
}

// ---------------- launch ---------------------------------------------------
extern "C" void kernel_launch(void* const* d_in, const int* in_sizes, int n_in,
                              void* d_out, int out_size)
{
    const float* x  = (const float*)d_in[0];
    const float* wq = (const float*)d_in[1];
    const float* wk = (const float*)d_in[2];
    const float* wv = (const float*)d_in[3];
    const float* wo = (const float*)d_in[4];
    const float* qn = (const float*)d_in[5];
    const float* kn = (const float*)d_in[6];
    const int* pos  = (const int*)d_in[7];
    float* out = (float*)d_out;

    unsigned short *xh, *wh, *oh, *af;
    cudaGetSymbolAddress((void**)&xh, g_xh);
    cudaGetSymbolAddress((void**)&wh, g_wh);
    cudaGetSymbolAddress((void**)&oh, g_oh);
    cudaGetSymbolAddress((void**)&af, g_af);

    cudaFuncSetAttribute(qkv_mma,  cudaFuncAttributeMaxDynamicSharedMemorySize, GEMM_SMEM);
    cudaFuncSetAttribute(gemm_mma, cudaFuncAttributeMaxDynamicSharedMemorySize, GEMM_SMEM);
    cudaFuncSetAttribute(attn_mma, cudaFuncAttributeMaxDynamicSharedMemorySize, ATT_SMEM);

    convert_all<<<18432, 256>>>((const float4*)x, (const float4*)wq,
                                (const float4*)wk, (const float4*)wv,
                                (const float4*)wo,
                                (uint2*)xh, (uint2*)wh, (uint2*)oh);

    qkv_mma<<<dim3(24, 32), 256, GEMM_SMEM>>>(xh, wh, qn, kn, pos);
    attn_mma<<<dim3(64, 16), 256, ATT_SMEM>>>();
    gemm_mma<<<dim3(16, 32), 256, GEMM_SMEM>>>(af, oh, out, Dd, Dd);
}